// round 2
// baseline (speedup 1.0000x reference)
#include <cuda_runtime.h>

// ---------------------------------------------------------------------------
// Problem constants (shapes fixed by the dataset)
// ---------------------------------------------------------------------------
#define NMAX   20000
#define EMAX   320000
#define ELMAX  100000
#define HEADS  8
#define CH     64
#define HC     512      // HEADS*CH
#define INCH   512

// ---------------------------------------------------------------------------
// Scratch (static device globals; no allocations allowed)
// ---------------------------------------------------------------------------
__device__ float        g_XLR[(size_t)NMAX * 1024];  // [:,0:512]=x@Wl, [:,512:1024]=x@Wr
__device__ float        g_ALPHA[(size_t)EMAX * HEADS];
__device__ unsigned int g_AMAX[NMAX * HEADS];        // monotone-uint encoded float max
__device__ float        g_DENOM[NMAX * HEADS];
__device__ float        g_OUT[(size_t)NMAX * HC];
__device__ float        g_SUM[HC];
__device__ float        g_SSQ[HC];
__device__ float        g_CA[HC];                    // BN scale
__device__ float        g_CB[HC];                    // BN shift

// ---------------------------------------------------------------------------
// Init: zero OUT / AMAX / DENOM / SUM / SSQ
// ---------------------------------------------------------------------------
__global__ void k_init(int n_nodes)
{
    int i = blockIdx.x * blockDim.x + threadIdx.x;
    int total = n_nodes * HC;
    if (i < total) g_OUT[i] = 0.0f;
    if (i < n_nodes * HEADS) { g_AMAX[i] = 0u; g_DENOM[i] = 0.0f; }
    if (i < HC) { g_SUM[i] = 0.0f; g_SSQ[i] = 0.0f; }
}

// ---------------------------------------------------------------------------
// SGEMM: g_XLR[M,1024] = x[M,512] @ [Wl | Wr]
// 128x128 block tile, BK=16, 256 threads, 8x8 per-thread microtile
// ---------------------------------------------------------------------------
__global__ __launch_bounds__(256) void k_gemm(const float* __restrict__ x,
                                              const float* __restrict__ Wl,
                                              const float* __restrict__ Wr,
                                              int M)
{
    __shared__ float As[16][128];   // transposed A tile: As[k][m]
    __shared__ float Bs[16][128];   // Bs[k][n]

    const int bn   = blockIdx.x;            // 0..7 over 1024 output cols
    const int row0 = blockIdx.y * 128;
    const float* W = (bn < 4) ? Wl : Wr;
    const int col0 = (bn & 3) * 128;        // column within the chosen W

    const int tid = threadIdx.x;
    const int a_r = tid >> 2;               // 0..63
    const int a_c = (tid & 3) << 2;         // 0,4,8,12
    const int b_r = tid >> 5;               // 0..7
    const int b_c = (tid & 31) << 2;        // 0..124
    const int ty  = tid >> 4;               // 0..15
    const int tx  = tid & 15;               // 0..15

    float acc[8][8];
#pragma unroll
    for (int i = 0; i < 8; i++)
#pragma unroll
        for (int j = 0; j < 8; j++) acc[i][j] = 0.0f;

    for (int k0 = 0; k0 < INCH; k0 += 16) {
        // load A tile (128 rows x 16 k), transpose into As
#pragma unroll
        for (int i = 0; i < 2; i++) {
            int r  = a_r + i * 64;
            int gr = row0 + r;
            float4 v = make_float4(0.f, 0.f, 0.f, 0.f);
            if (gr < M) v = *(const float4*)(x + (size_t)gr * INCH + k0 + a_c);
            As[a_c + 0][r] = v.x;
            As[a_c + 1][r] = v.y;
            As[a_c + 2][r] = v.z;
            As[a_c + 3][r] = v.w;
        }
        // load B tile (16 k x 128 cols)
#pragma unroll
        for (int i = 0; i < 2; i++) {
            int r = b_r + i * 8;
            *(float4*)&Bs[r][b_c] =
                *(const float4*)(W + (size_t)(k0 + r) * HC + col0 + b_c);
        }
        __syncthreads();

#pragma unroll
        for (int kk = 0; kk < 16; kk++) {
            float4 a0 = *(const float4*)&As[kk][ty * 8];
            float4 a1 = *(const float4*)&As[kk][ty * 8 + 4];
            float4 b0 = *(const float4*)&Bs[kk][tx * 8];
            float4 b1 = *(const float4*)&Bs[kk][tx * 8 + 4];
            float a[8] = {a0.x, a0.y, a0.z, a0.w, a1.x, a1.y, a1.z, a1.w};
            float b[8] = {b0.x, b0.y, b0.z, b0.w, b1.x, b1.y, b1.z, b1.w};
#pragma unroll
            for (int i = 0; i < 8; i++)
#pragma unroll
                for (int j = 0; j < 8; j++) acc[i][j] = fmaf(a[i], b[j], acc[i][j]);
        }
        __syncthreads();
    }

    const int gc0 = bn * 128 + tx * 8;
#pragma unroll
    for (int i = 0; i < 8; i++) {
        int gr = row0 + ty * 8 + i;
        if (gr < M) {
            float4 v0 = make_float4(acc[i][0], acc[i][1], acc[i][2], acc[i][3]);
            float4 v1 = make_float4(acc[i][4], acc[i][5], acc[i][6], acc[i][7]);
            *(float4*)(g_XLR + (size_t)gr * 1024 + gc0)     = v0;
            *(float4*)(g_XLR + (size_t)gr * 1024 + gc0 + 4) = v1;
        }
    }
}

// ---------------------------------------------------------------------------
// Per-edge attention logits + atomicMax into per-(dst,head) max
// One warp per edge. Lane covers channels v = h*64 + lane and +32.
// ---------------------------------------------------------------------------
__device__ __forceinline__ unsigned int enc_f(float f)
{
    unsigned int u = __float_as_uint(f);
    return (u & 0x80000000u) ? ~u : (u | 0x80000000u);
}
__device__ __forceinline__ float dec_f(unsigned int e)
{
    return (e & 0x80000000u) ? __uint_as_float(e ^ 0x80000000u)
                             : __uint_as_float(~e);
}

__global__ __launch_bounds__(256) void k_edge_logits(const int* __restrict__ src,
                                                     const int* __restrict__ dst,
                                                     const float* __restrict__ att,
                                                     int E)
{
    int w    = (blockIdx.x * blockDim.x + threadIdx.x) >> 5;
    int lane = threadIdx.x & 31;
    if (w >= E) return;
    int s = src[w], d = dst[w];
    const float* xl = g_XLR + (size_t)s * 1024;
    const float* xr = g_XLR + (size_t)d * 1024 + 512;

    float acc[HEADS];
#pragma unroll
    for (int h = 0; h < HEADS; h++) {
        int v0 = h * 64 + lane;
        int v1 = v0 + 32;
        float t0 = xl[v0] + xr[v0];
        float t1 = xl[v1] + xr[v1];
        t0 = (t0 > 0.f) ? t0 : 0.2f * t0;
        t1 = (t1 > 0.f) ? t1 : 0.2f * t1;
        acc[h] = t0 * __ldg(att + v0) + t1 * __ldg(att + v1);
    }
#pragma unroll
    for (int h = 0; h < HEADS; h++)
#pragma unroll
        for (int o = 16; o; o >>= 1)
            acc[h] += __shfl_xor_sync(0xffffffffu, acc[h], o);

    if (lane < HEADS) {
        float a = acc[lane];
        g_ALPHA[(size_t)w * HEADS + lane] = a;
        atomicMax(&g_AMAX[d * HEADS + lane], enc_f(a));
    }
}

// ---------------------------------------------------------------------------
// exp(alpha - amax[dst]) and atomicAdd into denom
// ---------------------------------------------------------------------------
__global__ void k_exp(const int* __restrict__ dst, int E)
{
    int i = blockIdx.x * blockDim.x + threadIdx.x;
    if (i >= E * HEADS) return;
    int e = i >> 3, h = i & 7;
    int d = dst[e];
    float m  = dec_f(g_AMAX[d * HEADS + h]);
    float ea = __expf(g_ALPHA[i] - m);
    g_ALPHA[i] = ea;
    atomicAdd(&g_DENOM[d * HEADS + h], ea);
}

// ---------------------------------------------------------------------------
// Aggregation: OUT[dst] += (alpha/denom) * xl[src]   (atomicAdd, warp/edge)
// ---------------------------------------------------------------------------
__global__ __launch_bounds__(256) void k_agg(const int* __restrict__ src,
                                             const int* __restrict__ dst,
                                             int E)
{
    int w    = (blockIdx.x * blockDim.x + threadIdx.x) >> 5;
    int lane = threadIdx.x & 31;
    if (w >= E) return;
    int s = src[w], d = dst[w];
    float wv = 0.f;
    if (lane < HEADS)
        wv = g_ALPHA[(size_t)w * HEADS + lane] /
             (g_DENOM[d * HEADS + lane] + 1e-16f);
    const float* xl = g_XLR + (size_t)s * 1024;
    float* o = g_OUT + (size_t)d * HC;
#pragma unroll
    for (int h = 0; h < HEADS; h++) {
        float wh = __shfl_sync(0xffffffffu, wv, h);
        int v0 = h * 64 + lane;
        atomicAdd(o + v0,      wh * xl[v0]);
        atomicAdd(o + v0 + 32, wh * xl[v0 + 32]);
    }
}

// ---------------------------------------------------------------------------
// BatchNorm statistics: per-channel sum / sumsq over nodes
// block = 512 threads (one per channel), each block handles a row chunk
// ---------------------------------------------------------------------------
__global__ __launch_bounds__(512) void k_bn_stats(int n_nodes, int rows_per)
{
    int j  = threadIdx.x;
    int r0 = blockIdx.x * rows_per;
    int r1 = min(r0 + rows_per, n_nodes);
    float s = 0.f, q = 0.f;
    for (int r = r0; r < r1; r++) {
        float v = g_OUT[(size_t)r * HC + j];
        s += v;
        q = fmaf(v, v, q);
    }
    atomicAdd(&g_SUM[j], s);
    atomicAdd(&g_SSQ[j], q);
}

// BN coefficients: a = gamma*rsqrt(var+eps), b = beta - mu*a
// (bias cancels: BN subtracts the mean, so a constant channel shift is a no-op)
__global__ void k_bn_coef(const float* __restrict__ gamma,
                          const float* __restrict__ beta, float invN)
{
    int j = threadIdx.x;
    float mu  = g_SUM[j] * invN;
    float var = g_SSQ[j] * invN - mu * mu;
    float a   = gamma[j] * rsqrtf(var + 1e-5f);
    g_CA[j] = a;
    g_CB[j] = beta[j] - mu * a;
}

// ---------------------------------------------------------------------------
// Link scoring: out[i] = sum_j relu(bn(OUT[s,j])) * relu(bn(OUT[t,j]))
// One warp per label edge, float4 loads, BN+ReLU applied on the fly.
// ---------------------------------------------------------------------------
__global__ __launch_bounds__(256) void k_score(const int* __restrict__ li,
                                               int EL, float* __restrict__ out)
{
    int w    = (blockIdx.x * blockDim.x + threadIdx.x) >> 5;
    int lane = threadIdx.x & 31;
    if (w >= EL) return;
    int s = li[w];
    int t = li[EL + w];
    const float4* ps = (const float4*)(g_OUT + (size_t)s * HC);
    const float4* pt = (const float4*)(g_OUT + (size_t)t * HC);
    float acc = 0.f;
#pragma unroll
    for (int k = 0; k < 4; k++) {
        int idx = lane + 32 * k;      // float4 index 0..127
        float4 a4 = ps[idx];
        float4 b4 = pt[idx];
        float4 ca = *(const float4*)(g_CA + idx * 4);
        float4 cb = *(const float4*)(g_CB + idx * 4);
        float sx = fmaxf(fmaf(a4.x, ca.x, cb.x), 0.f);
        float sy = fmaxf(fmaf(a4.y, ca.y, cb.y), 0.f);
        float sz = fmaxf(fmaf(a4.z, ca.z, cb.z), 0.f);
        float sw = fmaxf(fmaf(a4.w, ca.w, cb.w), 0.f);
        float tx = fmaxf(fmaf(b4.x, ca.x, cb.x), 0.f);
        float ty = fmaxf(fmaf(b4.y, ca.y, cb.y), 0.f);
        float tz = fmaxf(fmaf(b4.z, ca.z, cb.z), 0.f);
        float tw = fmaxf(fmaf(b4.w, ca.w, cb.w), 0.f);
        acc += sx * tx + sy * ty + sz * tz + sw * tw;
    }
#pragma unroll
    for (int o = 16; o; o >>= 1) acc += __shfl_xor_sync(0xffffffffu, acc, o);
    if (lane == 0) out[w] = acc;
}

// ---------------------------------------------------------------------------
// Launch
// ---------------------------------------------------------------------------
extern "C" void kernel_launch(void* const* d_in, const int* in_sizes, int n_in,
                              void* d_out, int out_size)
{
    const float* x     = (const float*)d_in[0];
    const int*   ei    = (const int*)d_in[1];
    const int*   eli   = (const int*)d_in[2];
    const float* Wl    = (const float*)d_in[3];
    const float* Wr    = (const float*)d_in[4];
    const float* att   = (const float*)d_in[5];
    // d_in[6] = bias (cancels under BatchNorm; unused)
    const float* gamma = (const float*)d_in[7];
    const float* beta  = (const float*)d_in[8];
    float* out = (float*)d_out;

    const int N  = in_sizes[0] / INCH;
    const int E  = in_sizes[1] / 2;
    const int EL = in_sizes[2] / 2;
    const int* src = ei;
    const int* dst = ei + E;

    // init scratch
    {
        int total = N * HC;
        k_init<<<(total + 255) / 256, 256>>>(N);
    }
    // GEMM
    {
        dim3 grid(8, (N + 127) / 128);
        k_gemm<<<grid, 256>>>(x, Wl, Wr, N);
    }
    // edge logits + max
    k_edge_logits<<<(E * 32 + 255) / 256, 256>>>(src, dst, att, E);
    // exp + denom
    k_exp<<<(E * HEADS + 255) / 256, 256>>>(dst, E);
    // aggregation
    k_agg<<<(E * 32 + 255) / 256, 256>>>(src, dst, E);
    // batchnorm stats + coefficients
    {
        int rows_per = 200;
        int blocks = (N + rows_per - 1) / rows_per;
        k_bn_stats<<<blocks, 512>>>(N, rows_per);
        k_bn_coef<<<1, HC>>>(gamma, beta, 1.0f / (float)N);
    }
    // scoring
    k_score<<<(EL * 32 + 255) / 256, 256>>>(eli, EL, out);
}

// round 4
// speedup vs baseline: 1.7927x; 1.7927x over previous
#include <cuda_runtime.h>

// ---------------------------------------------------------------------------
// Problem constants
// ---------------------------------------------------------------------------
#define NMAX   20000
#define EMAX   320000
#define HEADS  8
#define CH     64
#define HC     512
#define INCH   512

// ---------------------------------------------------------------------------
// Scratch (static device globals; no allocations allowed)
// ---------------------------------------------------------------------------
__device__ float g_XLR[(size_t)NMAX * 1024];   // [:,0:512]=x@Wl, [:,512:1024]=x@Wr
__device__ float g_ALPHA[(size_t)EMAX * HEADS];// CSR-ordered logits -> exp values
__device__ int   g_DEG[NMAX];
__device__ int   g_START[NMAX];
__device__ int   g_CURSOR[NMAX];
__device__ int   g_CSRC[EMAX];                 // CSR source-node list
__device__ float g_OUT[(size_t)NMAX * HC];
__device__ float g_SUM[HC];
__device__ float g_SSQ[HC];
__device__ float g_CA[HC];
__device__ float g_CB[HC];

// ---------------------------------------------------------------------------
// init: zero degree histogram + BN accumulators
// ---------------------------------------------------------------------------
__global__ void k_zero(int N)
{
    int i = blockIdx.x * blockDim.x + threadIdx.x;
    if (i < N) g_DEG[i] = 0;
    if (i < HC) { g_SUM[i] = 0.f; g_SSQ[i] = 0.f; }
}

// ---------------------------------------------------------------------------
// tf32 helpers
// ---------------------------------------------------------------------------
__device__ __forceinline__ float to_tf32(float f)
{
    unsigned u;
    asm("cvt.rna.tf32.f32 %0, %1;" : "=r"(u) : "f"(f));
    return __uint_as_float(u);
}

__device__ __forceinline__ void mma_tf32(float c[4], const float a[4], const float b[2])
{
    asm volatile(
        "mma.sync.aligned.m16n8k8.row.col.f32.tf32.tf32.f32 "
        "{%0,%1,%2,%3},{%4,%5,%6,%7},{%8,%9},{%0,%1,%2,%3};"
        : "+f"(c[0]), "+f"(c[1]), "+f"(c[2]), "+f"(c[3])
        : "r"(__float_as_uint(a[0])), "r"(__float_as_uint(a[1])),
          "r"(__float_as_uint(a[2])), "r"(__float_as_uint(a[3])),
          "r"(__float_as_uint(b[0])), "r"(__float_as_uint(b[1])));
}

// ---------------------------------------------------------------------------
// tf32 GEMM: g_XLR[M,1024] = x[M,512] @ [Wl | Wr]
// block tile 128x128, BK=16, 256 thr = 8 warps, warp tile 32x64
// ---------------------------------------------------------------------------
#define APAD 132
__global__ __launch_bounds__(256) void k_gemm(const float* __restrict__ x,
                                              const float* __restrict__ Wl,
                                              const float* __restrict__ Wr,
                                              int M)
{
    __shared__ float As[16][APAD];   // As[k][m], tf32-rounded
    __shared__ float Bs[16][APAD];   // Bs[k][n], tf32-rounded

    const int bn   = blockIdx.x;                 // 0..7 over 1024 cols
    const int row0 = blockIdx.y * 128;
    const float* W = (bn < 4) ? Wl : Wr;
    const int col0 = (bn & 3) * 128;

    const int tid  = threadIdx.x;
    const int warp = tid >> 5;
    const int lane = tid & 31;
    const int wm   = warp >> 1;                  // 0..3  (rows of 32)
    const int wn   = warp & 1;                   // 0..1  (cols of 64)
    const int gid  = lane >> 2;                  // 0..7
    const int tig  = lane & 3;                   // 0..3

    const int a_r = tid >> 2;                    // 0..63
    const int a_c = (tid & 3) << 2;              // 0,4,8,12
    const int b_r = tid >> 5;                    // 0..7
    const int b_c = (tid & 31) << 2;             // 0..124

    float c[2][8][4];
#pragma unroll
    for (int i = 0; i < 2; i++)
#pragma unroll
        for (int j = 0; j < 8; j++)
#pragma unroll
            for (int q = 0; q < 4; q++) c[i][j][q] = 0.f;

    for (int k0 = 0; k0 < INCH; k0 += 16) {
#pragma unroll
        for (int i = 0; i < 2; i++) {
            int r  = a_r + i * 64;
            int gr = row0 + r;
            float4 v = make_float4(0.f, 0.f, 0.f, 0.f);
            if (gr < M) v = *(const float4*)(x + (size_t)gr * INCH + k0 + a_c);
            As[a_c + 0][r] = to_tf32(v.x);
            As[a_c + 1][r] = to_tf32(v.y);
            As[a_c + 2][r] = to_tf32(v.z);
            As[a_c + 3][r] = to_tf32(v.w);
        }
#pragma unroll
        for (int i = 0; i < 2; i++) {
            int r = b_r + i * 8;
            float4 v = *(const float4*)(W + (size_t)(k0 + r) * HC + col0 + b_c);
            Bs[r][b_c + 0] = to_tf32(v.x);
            Bs[r][b_c + 1] = to_tf32(v.y);
            Bs[r][b_c + 2] = to_tf32(v.z);
            Bs[r][b_c + 3] = to_tf32(v.w);
        }
        __syncthreads();

#pragma unroll
        for (int ks = 0; ks < 16; ks += 8) {
            float a[2][4];
#pragma unroll
            for (int mt = 0; mt < 2; mt++) {
                int mr = wm * 32 + mt * 16 + gid;
                a[mt][0] = As[ks + tig][mr];
                a[mt][1] = As[ks + tig][mr + 8];
                a[mt][2] = As[ks + tig + 4][mr];
                a[mt][3] = As[ks + tig + 4][mr + 8];
            }
            float b[8][2];
#pragma unroll
            for (int nt = 0; nt < 8; nt++) {
                int nc = wn * 64 + nt * 8 + gid;
                b[nt][0] = Bs[ks + tig][nc];
                b[nt][1] = Bs[ks + tig + 4][nc];
            }
#pragma unroll
            for (int mt = 0; mt < 2; mt++)
#pragma unroll
                for (int nt = 0; nt < 8; nt++)
                    mma_tf32(c[mt][nt], a[mt], b[nt]);
        }
        __syncthreads();
    }

    // store C
#pragma unroll
    for (int mt = 0; mt < 2; mt++) {
#pragma unroll
        for (int nt = 0; nt < 8; nt++) {
            int r   = row0 + wm * 32 + mt * 16 + gid;
            int col = bn * 128 + wn * 64 + nt * 8 + 2 * tig;
            if (r < M)
                *(float2*)(g_XLR + (size_t)r * 1024 + col) =
                    make_float2(c[mt][nt][0], c[mt][nt][1]);
            if (r + 8 < M)
                *(float2*)(g_XLR + (size_t)(r + 8) * 1024 + col) =
                    make_float2(c[mt][nt][2], c[mt][nt][3]);
        }
    }
}

// ---------------------------------------------------------------------------
// CSR build: histogram -> scan -> scatter
// ---------------------------------------------------------------------------
__global__ void k_hist(const int* __restrict__ dst, int E)
{
    int e = blockIdx.x * blockDim.x + threadIdx.x;
    if (e < E) atomicAdd(&g_DEG[dst[e]], 1);
}

__global__ __launch_bounds__(1024) void k_scan(int N)
{
    __shared__ int sm[1024];
    int t = threadIdx.x;
    int chunk = (N + 1023) / 1024;
    int lo = t * chunk, hi = min(lo + chunk, N);
    int s = 0;
    for (int i = lo; i < hi; i++) s += g_DEG[i];
    sm[t] = s;
    __syncthreads();
    for (int off = 1; off < 1024; off <<= 1) {
        int v = (t >= off) ? sm[t - off] : 0;
        __syncthreads();
        sm[t] += v;
        __syncthreads();
    }
    int base = (t == 0) ? 0 : sm[t - 1];
    for (int i = lo; i < hi; i++) {
        g_START[i]  = base;
        g_CURSOR[i] = base;
        base += g_DEG[i];
    }
}

__global__ void k_scatter(const int* __restrict__ src,
                          const int* __restrict__ dst, int E)
{
    int e = blockIdx.x * blockDim.x + threadIdx.x;
    if (e >= E) return;
    int d   = dst[e];
    int pos = atomicAdd(&g_CURSOR[d], 1);
    g_CSRC[pos] = src[e];
}

// ---------------------------------------------------------------------------
// Fused GATv2 softmax + aggregation: one warp per destination node.
// Lane owns channels c = lane*4 + 128*k, k=0..3 (float4, fully coalesced).
// Head of those channels: h = 2*k + (lane>>4).
// ---------------------------------------------------------------------------
__global__ __launch_bounds__(256) void k_edge(const float* __restrict__ att, int N)
{
    int w    = (blockIdx.x * blockDim.x + threadIdx.x) >> 5;
    int lane = threadIdx.x & 31;
    if (w >= N) return;
    const int d     = w;
    const int start = g_START[d];
    const int deg   = g_DEG[d];
    const int c0    = lane * 4;

    // cache att and xr[d]
    float4 attv[4], xrv[4];
#pragma unroll
    for (int k = 0; k < 4; k++) {
        attv[k] = __ldg((const float4*)(att + c0 + 128 * k));
        xrv[k]  = *(const float4*)(g_XLR + (size_t)d * 1024 + 512 + c0 + 128 * k);
    }

    float m0 = -1e30f, m1 = -1e30f, m2 = -1e30f, m3 = -1e30f;
    float m4 = -1e30f, m5 = -1e30f, m6 = -1e30f, m7 = -1e30f;

    // ---- pass 1: logits, running max, store raw logits ----
    for (int j = 0; j < deg; j++) {
        int s = g_CSRC[start + j];
        const float* xl = g_XLR + (size_t)s * 1024;
        float p[4];
#pragma unroll
        for (int k = 0; k < 4; k++) {
            float4 v = *(const float4*)(xl + c0 + 128 * k);
            float tx = v.x + xrv[k].x, ty = v.y + xrv[k].y;
            float tz = v.z + xrv[k].z, tw = v.w + xrv[k].w;
            tx = (tx > 0.f) ? tx : 0.2f * tx;
            ty = (ty > 0.f) ? ty : 0.2f * ty;
            tz = (tz > 0.f) ? tz : 0.2f * tz;
            tw = (tw > 0.f) ? tw : 0.2f * tw;
            p[k] = tx * attv[k].x + ty * attv[k].y + tz * attv[k].z + tw * attv[k].w;
        }
        // reduce within 16-lane halves (head 2k in lanes 0-15, 2k+1 in 16-31)
#pragma unroll
        for (int k = 0; k < 4; k++) {
            p[k] += __shfl_xor_sync(0xffffffffu, p[k], 1);
            p[k] += __shfl_xor_sync(0xffffffffu, p[k], 2);
            p[k] += __shfl_xor_sync(0xffffffffu, p[k], 4);
            p[k] += __shfl_xor_sync(0xffffffffu, p[k], 8);
        }
        float a0 = __shfl_sync(0xffffffffu, p[0], 0);
        float a1 = __shfl_sync(0xffffffffu, p[0], 16);
        float a2 = __shfl_sync(0xffffffffu, p[1], 0);
        float a3 = __shfl_sync(0xffffffffu, p[1], 16);
        float a4 = __shfl_sync(0xffffffffu, p[2], 0);
        float a5 = __shfl_sync(0xffffffffu, p[2], 16);
        float a6 = __shfl_sync(0xffffffffu, p[3], 0);
        float a7 = __shfl_sync(0xffffffffu, p[3], 16);
        m0 = fmaxf(m0, a0); m1 = fmaxf(m1, a1);
        m2 = fmaxf(m2, a2); m3 = fmaxf(m3, a3);
        m4 = fmaxf(m4, a4); m5 = fmaxf(m5, a5);
        m6 = fmaxf(m6, a6); m7 = fmaxf(m7, a7);
        float av = (lane == 1) ? a1 : (lane == 2) ? a2 : (lane == 3) ? a3 :
                   (lane == 4) ? a4 : (lane == 5) ? a5 : (lane == 6) ? a6 :
                   (lane == 7) ? a7 : a0;
        if (lane < 8) g_ALPHA[(size_t)(start + j) * 8 + lane] = av;
    }

    // ---- pass 2: exp + denom (4 edges x 8 heads per iteration) ----
    int hh = lane & 7;
    float msel = (hh == 1) ? m1 : (hh == 2) ? m2 : (hh == 3) ? m3 :
                 (hh == 4) ? m4 : (hh == 5) ? m5 : (hh == 6) ? m6 :
                 (hh == 7) ? m7 : m0;
    float dpart = 0.f;
    for (int j0 = 0; j0 < deg; j0 += 4) {
        int e = j0 + (lane >> 3);
        if (e < deg) {
            size_t idx = (size_t)(start + e) * 8 + hh;
            float ea = __expf(g_ALPHA[idx] - msel);
            g_ALPHA[idx] = ea;
            dpart += ea;
        }
    }
    dpart += __shfl_xor_sync(0xffffffffu, dpart, 8);
    dpart += __shfl_xor_sync(0xffffffffu, dpart, 16);
    float invd = 1.0f / (dpart + 1e-16f);   // lane<8: denom for head==lane

    // ---- pass 3: weighted aggregation ----
    float4 acc[4];
#pragma unroll
    for (int k = 0; k < 4; k++) acc[k] = make_float4(0.f, 0.f, 0.f, 0.f);

    for (int j = 0; j < deg; j++) {
        int s = g_CSRC[start + j];
        float wv = 0.f;
        if (lane < 8) wv = g_ALPHA[(size_t)(start + j) * 8 + lane] * invd;
        const float* xl = g_XLR + (size_t)s * 1024;
#pragma unroll
        for (int k = 0; k < 4; k++) {
            float wh = __shfl_sync(0xffffffffu, wv, 2 * k + (lane >> 4));
            float4 v = *(const float4*)(xl + c0 + 128 * k);
            acc[k].x = fmaf(wh, v.x, acc[k].x);
            acc[k].y = fmaf(wh, v.y, acc[k].y);
            acc[k].z = fmaf(wh, v.z, acc[k].z);
            acc[k].w = fmaf(wh, v.w, acc[k].w);
        }
    }
#pragma unroll
    for (int k = 0; k < 4; k++)
        *(float4*)(g_OUT + (size_t)d * HC + c0 + 128 * k) = acc[k];
}

// ---------------------------------------------------------------------------
// BatchNorm stats / coefficients
// ---------------------------------------------------------------------------
__global__ __launch_bounds__(512) void k_bn_stats(int n_nodes, int rows_per)
{
    int j  = threadIdx.x;
    int r0 = blockIdx.x * rows_per;
    int r1 = min(r0 + rows_per, n_nodes);
    float s = 0.f, q = 0.f;
    for (int r = r0; r < r1; r++) {
        float v = g_OUT[(size_t)r * HC + j];
        s += v;
        q = fmaf(v, v, q);
    }
    atomicAdd(&g_SUM[j], s);
    atomicAdd(&g_SSQ[j], q);
}

__global__ void k_bn_coef(const float* __restrict__ gamma,
                          const float* __restrict__ beta, float invN)
{
    int j = threadIdx.x;
    float mu  = g_SUM[j] * invN;
    float var = g_SSQ[j] * invN - mu * mu;
    float a   = gamma[j] * rsqrtf(var + 1e-5f);
    g_CA[j] = a;
    g_CB[j] = beta[j] - mu * a;
}

// ---------------------------------------------------------------------------
// Link scoring
// ---------------------------------------------------------------------------
__global__ __launch_bounds__(256) void k_score(const int* __restrict__ li,
                                               int EL, float* __restrict__ out)
{
    int w    = (blockIdx.x * blockDim.x + threadIdx.x) >> 5;
    int lane = threadIdx.x & 31;
    if (w >= EL) return;
    int s = li[w];
    int t = li[EL + w];
    const float4* ps = (const float4*)(g_OUT + (size_t)s * HC);
    const float4* pt = (const float4*)(g_OUT + (size_t)t * HC);
    float acc = 0.f;
#pragma unroll
    for (int k = 0; k < 4; k++) {
        int idx = lane + 32 * k;
        float4 a4 = ps[idx];
        float4 b4 = pt[idx];
        float4 ca = *(const float4*)(g_CA + idx * 4);
        float4 cb = *(const float4*)(g_CB + idx * 4);
        float sx = fmaxf(fmaf(a4.x, ca.x, cb.x), 0.f);
        float sy = fmaxf(fmaf(a4.y, ca.y, cb.y), 0.f);
        float sz = fmaxf(fmaf(a4.z, ca.z, cb.z), 0.f);
        float sw = fmaxf(fmaf(a4.w, ca.w, cb.w), 0.f);
        float tx = fmaxf(fmaf(b4.x, ca.x, cb.x), 0.f);
        float ty = fmaxf(fmaf(b4.y, ca.y, cb.y), 0.f);
        float tz = fmaxf(fmaf(b4.z, ca.z, cb.z), 0.f);
        float tw = fmaxf(fmaf(b4.w, ca.w, cb.w), 0.f);
        acc += sx * tx + sy * ty + sz * tz + sw * tw;
    }
#pragma unroll
    for (int o = 16; o; o >>= 1) acc += __shfl_xor_sync(0xffffffffu, acc, o);
    if (lane == 0) out[w] = acc;
}

// ---------------------------------------------------------------------------
// Launch
// ---------------------------------------------------------------------------
extern "C" void kernel_launch(void* const* d_in, const int* in_sizes, int n_in,
                              void* d_out, int out_size)
{
    const float* x     = (const float*)d_in[0];
    const int*   ei    = (const int*)d_in[1];
    const int*   eli   = (const int*)d_in[2];
    const float* Wl    = (const float*)d_in[3];
    const float* Wr    = (const float*)d_in[4];
    const float* att   = (const float*)d_in[5];
    // d_in[6] = bias: cancels under BatchNorm (mean-subtracted), unused
    const float* gamma = (const float*)d_in[7];
    const float* beta  = (const float*)d_in[8];
    float* out = (float*)d_out;

    const int N  = in_sizes[0] / INCH;
    const int E  = in_sizes[1] / 2;
    const int EL = in_sizes[2] / 2;
    const int* src = ei;
    const int* dst = ei + E;

    k_zero<<<(N + 255) / 256, 256>>>(N);

    {
        dim3 grid(8, (N + 127) / 128);
        k_gemm<<<grid, 256>>>(x, Wl, Wr, N);
    }

    k_hist<<<(E + 255) / 256, 256>>>(dst, E);
    k_scan<<<1, 1024>>>(N);
    k_scatter<<<(E + 255) / 256, 256>>>(src, dst, E);

    k_edge<<<(N * 32 + 255) / 256, 256>>>(att, N);

    {
        int rows_per = 40;
        int blocks = (N + rows_per - 1) / rows_per;
        k_bn_stats<<<blocks, 512>>>(N, rows_per);
        k_bn_coef<<<1, HC>>>(gamma, beta, 1.0f / (float)N);
    }

    k_score<<<(EL * 32 + 255) / 256, 256>>>(eli, EL, out);
}

// round 5
// speedup vs baseline: 2.1740x; 1.2127x over previous
#include <cuda_runtime.h>

// ---------------------------------------------------------------------------
// Problem constants
// ---------------------------------------------------------------------------
#define NMAX   20000
#define EMAX   320000
#define HEADS  8
#define CH     64
#define HC     512
#define INCH   512
#define NB_SCAN ((NMAX + 255) / 256)

// ---------------------------------------------------------------------------
// Scratch (static device globals; no allocations allowed)
// ---------------------------------------------------------------------------
__device__ float g_XLR[(size_t)NMAX * 1024];   // [:,0:512]=x@Wl, [:,512:1024]=x@Wr
__device__ int   g_DEG[NMAX];
__device__ int   g_START[NMAX];
__device__ int   g_CURSOR[NMAX];
__device__ int   g_CSRC[EMAX];                 // CSR source-node list
__device__ int   g_PART[NB_SCAN];
__device__ float g_OUT[(size_t)NMAX * HC];
__device__ float g_SUM[HC];
__device__ float g_SSQ[HC];
__device__ float g_CA[HC];
__device__ float g_CB[HC];

// ---------------------------------------------------------------------------
// init: zero degree histogram + BN accumulators
// ---------------------------------------------------------------------------
__global__ void k_zero(int N)
{
    int i = blockIdx.x * blockDim.x + threadIdx.x;
    if (i < N) g_DEG[i] = 0;
    if (i < HC) { g_SUM[i] = 0.f; g_SSQ[i] = 0.f; }
}

// ---------------------------------------------------------------------------
// tf32 helpers
// ---------------------------------------------------------------------------
__device__ __forceinline__ float to_tf32(float f)
{
    unsigned u;
    asm("cvt.rna.tf32.f32 %0, %1;" : "=r"(u) : "f"(f));
    return __uint_as_float(u);
}

__device__ __forceinline__ void mma_tf32(float c[4], const float a[4], const float b[2])
{
    asm volatile(
        "mma.sync.aligned.m16n8k8.row.col.f32.tf32.tf32.f32 "
        "{%0,%1,%2,%3},{%4,%5,%6,%7},{%8,%9},{%0,%1,%2,%3};"
        : "+f"(c[0]), "+f"(c[1]), "+f"(c[2]), "+f"(c[3])
        : "r"(__float_as_uint(a[0])), "r"(__float_as_uint(a[1])),
          "r"(__float_as_uint(a[2])), "r"(__float_as_uint(a[3])),
          "r"(__float_as_uint(b[0])), "r"(__float_as_uint(b[1])));
}

// ---------------------------------------------------------------------------
// tf32 GEMM, double-buffered: g_XLR[M,1024] = x[M,512] @ [Wl | Wr]
// block tile 128x128, BK=16, 256 thr = 8 warps, warp tile 32x64
// ---------------------------------------------------------------------------
#define APAD 132
__global__ __launch_bounds__(256) void k_gemm(const float* __restrict__ x,
                                              const float* __restrict__ Wl,
                                              const float* __restrict__ Wr,
                                              int M)
{
    __shared__ float As[2][16][APAD];   // As[s][k][m], tf32-rounded
    __shared__ float Bs[2][16][APAD];   // Bs[s][k][n]

    const int bn   = blockIdx.x;                 // 0..7 over 1024 cols
    const int row0 = blockIdx.y * 128;
    const float* W = (bn < 4) ? Wl : Wr;
    const int col0 = (bn & 3) * 128;

    const int tid  = threadIdx.x;
    const int warp = tid >> 5;
    const int lane = tid & 31;
    const int wm   = warp >> 1;                  // 0..3
    const int wn   = warp & 1;                   // 0..1
    const int gid  = lane >> 2;                  // 0..7
    const int tig  = lane & 3;                   // 0..3

    const int a_r = tid >> 2;                    // 0..63
    const int a_c = (tid & 3) << 2;              // 0,4,8,12
    const int b_r = tid >> 5;                    // 0..7
    const int b_c = (tid & 31) << 2;             // 0..124

    float c[2][8][4];
#pragma unroll
    for (int i = 0; i < 2; i++)
#pragma unroll
        for (int j = 0; j < 8; j++)
#pragma unroll
            for (int q = 0; q < 4; q++) c[i][j][q] = 0.f;

    float4 va[2], vb[2];

    // prologue: load k0=0 tile
#pragma unroll
    for (int i = 0; i < 2; i++) {
        int gr = row0 + a_r + i * 64;
        va[i] = make_float4(0.f, 0.f, 0.f, 0.f);
        if (gr < M) va[i] = *(const float4*)(x + (size_t)gr * INCH + a_c);
        vb[i] = *(const float4*)(W + (size_t)(b_r + i * 8) * HC + col0 + b_c);
    }
#pragma unroll
    for (int i = 0; i < 2; i++) {
        int r = a_r + i * 64;
        As[0][a_c + 0][r] = to_tf32(va[i].x);
        As[0][a_c + 1][r] = to_tf32(va[i].y);
        As[0][a_c + 2][r] = to_tf32(va[i].z);
        As[0][a_c + 3][r] = to_tf32(va[i].w);
        int br = b_r + i * 8;
        Bs[0][br][b_c + 0] = to_tf32(vb[i].x);
        Bs[0][br][b_c + 1] = to_tf32(vb[i].y);
        Bs[0][br][b_c + 2] = to_tf32(vb[i].z);
        Bs[0][br][b_c + 3] = to_tf32(vb[i].w);
    }
    __syncthreads();

    int buf = 0;
    for (int k0 = 0; k0 < INCH; k0 += 16) {
        const bool last = (k0 + 16 >= INCH);
        if (!last) {
#pragma unroll
            for (int i = 0; i < 2; i++) {
                int gr = row0 + a_r + i * 64;
                va[i] = make_float4(0.f, 0.f, 0.f, 0.f);
                if (gr < M)
                    va[i] = *(const float4*)(x + (size_t)gr * INCH + k0 + 16 + a_c);
                vb[i] = *(const float4*)(W + (size_t)(k0 + 16 + b_r + i * 8) * HC +
                                         col0 + b_c);
            }
        }

#pragma unroll
        for (int ks = 0; ks < 16; ks += 8) {
            float a[2][4];
#pragma unroll
            for (int mt = 0; mt < 2; mt++) {
                int mr = wm * 32 + mt * 16 + gid;
                a[mt][0] = As[buf][ks + tig][mr];
                a[mt][1] = As[buf][ks + tig][mr + 8];
                a[mt][2] = As[buf][ks + tig + 4][mr];
                a[mt][3] = As[buf][ks + tig + 4][mr + 8];
            }
            float b[8][2];
#pragma unroll
            for (int nt = 0; nt < 8; nt++) {
                int nc = wn * 64 + nt * 8 + gid;
                b[nt][0] = Bs[buf][ks + tig][nc];
                b[nt][1] = Bs[buf][ks + tig + 4][nc];
            }
#pragma unroll
            for (int mt = 0; mt < 2; mt++)
#pragma unroll
                for (int nt = 0; nt < 8; nt++)
                    mma_tf32(c[mt][nt], a[mt], b[nt]);
        }

        if (!last) {
            int nb = buf ^ 1;
#pragma unroll
            for (int i = 0; i < 2; i++) {
                int r = a_r + i * 64;
                As[nb][a_c + 0][r] = to_tf32(va[i].x);
                As[nb][a_c + 1][r] = to_tf32(va[i].y);
                As[nb][a_c + 2][r] = to_tf32(va[i].z);
                As[nb][a_c + 3][r] = to_tf32(va[i].w);
                int br = b_r + i * 8;
                Bs[nb][br][b_c + 0] = to_tf32(vb[i].x);
                Bs[nb][br][b_c + 1] = to_tf32(vb[i].y);
                Bs[nb][br][b_c + 2] = to_tf32(vb[i].z);
                Bs[nb][br][b_c + 3] = to_tf32(vb[i].w);
            }
            __syncthreads();
            buf = nb;
        }
    }

    // store C
#pragma unroll
    for (int mt = 0; mt < 2; mt++) {
#pragma unroll
        for (int nt = 0; nt < 8; nt++) {
            int r   = row0 + wm * 32 + mt * 16 + gid;
            int col = bn * 128 + wn * 64 + nt * 8 + 2 * tig;
            if (r < M)
                *(float2*)(g_XLR + (size_t)r * 1024 + col) =
                    make_float2(c[mt][nt][0], c[mt][nt][1]);
            if (r + 8 < M)
                *(float2*)(g_XLR + (size_t)(r + 8) * 1024 + col) =
                    make_float2(c[mt][nt][2], c[mt][nt][3]);
        }
    }
}

// ---------------------------------------------------------------------------
// CSR build: histogram -> parallel scan (partials + rebase) -> scatter
// ---------------------------------------------------------------------------
__global__ void k_hist(const int* __restrict__ dst, int E)
{
    int e = blockIdx.x * blockDim.x + threadIdx.x;
    if (e < E) atomicAdd(&g_DEG[dst[e]], 1);
}

__global__ __launch_bounds__(256) void k_scan_part(int N)
{
    __shared__ int wsum[8];
    int i = blockIdx.x * 256 + threadIdx.x;
    int v = (i < N) ? g_DEG[i] : 0;
    int lane = threadIdx.x & 31, wid = threadIdx.x >> 5;
#pragma unroll
    for (int o = 16; o; o >>= 1) v += __shfl_xor_sync(0xffffffffu, v, o);
    if (lane == 0) wsum[wid] = v;
    __syncthreads();
    if (threadIdx.x == 0) {
        int s = 0;
#pragma unroll
        for (int w2 = 0; w2 < 8; w2++) s += wsum[w2];
        g_PART[blockIdx.x] = s;
    }
}

__global__ __launch_bounds__(256) void k_scan_final(int N, int nb)
{
    __shared__ int wsum[8];
    __shared__ int wscan[8];
    __shared__ int sh_base;
    const int b = blockIdx.x;
    const int t = threadIdx.x;
    const int lane = t & 31, wid = t >> 5;

    // base = sum of partials before this block
    int ps = 0;
    for (int i = t; i < b; i += 256) ps += g_PART[i];
#pragma unroll
    for (int o = 16; o; o >>= 1) ps += __shfl_xor_sync(0xffffffffu, ps, o);
    if (lane == 0) wsum[wid] = ps;
    __syncthreads();
    if (t == 0) {
        int s = 0;
#pragma unroll
        for (int w2 = 0; w2 < 8; w2++) s += wsum[w2];
        sh_base = s;
    }
    __syncthreads();
    const int base = sh_base;

    // local exclusive scan of 256 degree values
    int i = b * 256 + t;
    int v = (i < N) ? g_DEG[i] : 0;
    int xinc = v;
#pragma unroll
    for (int o = 1; o < 32; o <<= 1) {
        int y = __shfl_up_sync(0xffffffffu, xinc, o);
        if (lane >= o) xinc += y;
    }
    if (lane == 31) wscan[wid] = xinc;
    __syncthreads();
    int off = 0;
#pragma unroll
    for (int w2 = 0; w2 < 8; w2++) off += (w2 < wid) ? wscan[w2] : 0;
    if (i < N) {
        int e = base + off + xinc - v;
        g_START[i]  = e;
        g_CURSOR[i] = e;
    }
}

__global__ void k_scatter(const int* __restrict__ src,
                          const int* __restrict__ dst, int E)
{
    int e = blockIdx.x * blockDim.x + threadIdx.x;
    if (e >= E) return;
    int d   = dst[e];
    int pos = atomicAdd(&g_CURSOR[d], 1);
    g_CSRC[pos] = src[e];
}

// ---------------------------------------------------------------------------
// Fused GATv2 with ONLINE softmax: single pass over each node's edges.
// One warp per destination node. Lane owns channels c = lane*4 + 128*k.
// After the 16-lane butterfly, each lane holds the logit of ITS OWN head
// hk = 2k + (lane>>4), so max/denom/acc update is fully lane-local.
// ---------------------------------------------------------------------------
__global__ __launch_bounds__(256) void k_edge(const float* __restrict__ att, int N)
{
    int w    = (blockIdx.x * blockDim.x + threadIdx.x) >> 5;
    int lane = threadIdx.x & 31;
    if (w >= N) return;
    const int d     = w;
    const int start = g_START[d];
    const int deg   = g_DEG[d];
    const int c0    = lane * 4;

    float4 attv[4], xrv[4];
#pragma unroll
    for (int k = 0; k < 4; k++) {
        attv[k] = __ldg((const float4*)(att + c0 + 128 * k));
        xrv[k]  = *(const float4*)(g_XLR + (size_t)d * 1024 + 512 + c0 + 128 * k);
    }

    float  m[4], dnm[4];
    float4 acc[4];
#pragma unroll
    for (int k = 0; k < 4; k++) {
        m[k] = -1e30f; dnm[k] = 0.f;
        acc[k] = make_float4(0.f, 0.f, 0.f, 0.f);
    }

    for (int j = 0; j < deg; j++) {
        int s = g_CSRC[start + j];
        const float* xl = g_XLR + (size_t)s * 1024;
        float4 v[4];
        float  p[4];
#pragma unroll
        for (int k = 0; k < 4; k++) {
            v[k] = *(const float4*)(xl + c0 + 128 * k);
            float tx = v[k].x + xrv[k].x, ty = v[k].y + xrv[k].y;
            float tz = v[k].z + xrv[k].z, tw = v[k].w + xrv[k].w;
            tx = (tx > 0.f) ? tx : 0.2f * tx;
            ty = (ty > 0.f) ? ty : 0.2f * ty;
            tz = (tz > 0.f) ? tz : 0.2f * tz;
            tw = (tw > 0.f) ? tw : 0.2f * tw;
            p[k] = tx * attv[k].x + ty * attv[k].y + tz * attv[k].z + tw * attv[k].w;
        }
        // butterfly over 16-lane halves: lane ends with logit of head 2k+(lane>>4)
#pragma unroll
        for (int k = 0; k < 4; k++) {
            p[k] += __shfl_xor_sync(0xffffffffu, p[k], 1);
            p[k] += __shfl_xor_sync(0xffffffffu, p[k], 2);
            p[k] += __shfl_xor_sync(0xffffffffu, p[k], 4);
            p[k] += __shfl_xor_sync(0xffffffffu, p[k], 8);
        }
        // online softmax update (lane-local, warp-uniform within 16-lane half)
#pragma unroll
        for (int k = 0; k < 4; k++) {
            float mn = fmaxf(m[k], p[k]);
            float r  = __expf(m[k] - mn);
            float e  = __expf(p[k] - mn);
            dnm[k]   = fmaf(dnm[k], r, e);
            acc[k].x = fmaf(acc[k].x, r, e * v[k].x);
            acc[k].y = fmaf(acc[k].y, r, e * v[k].y);
            acc[k].z = fmaf(acc[k].z, r, e * v[k].z);
            acc[k].w = fmaf(acc[k].w, r, e * v[k].w);
            m[k] = mn;
        }
    }

#pragma unroll
    for (int k = 0; k < 4; k++) {
        float inv = 1.0f / (dnm[k] + 1e-16f);
        float4 o = make_float4(acc[k].x * inv, acc[k].y * inv,
                               acc[k].z * inv, acc[k].w * inv);
        *(float4*)(g_OUT + (size_t)d * HC + c0 + 128 * k) = o;
    }
}

// ---------------------------------------------------------------------------
// BatchNorm stats / coefficients
// ---------------------------------------------------------------------------
__global__ __launch_bounds__(512) void k_bn_stats(int n_nodes, int rows_per)
{
    int j  = threadIdx.x;
    int r0 = blockIdx.x * rows_per;
    int r1 = min(r0 + rows_per, n_nodes);
    float s = 0.f, q = 0.f;
    for (int r = r0; r < r1; r++) {
        float v = g_OUT[(size_t)r * HC + j];
        s += v;
        q = fmaf(v, v, q);
    }
    atomicAdd(&g_SUM[j], s);
    atomicAdd(&g_SSQ[j], q);
}

__global__ void k_bn_coef(const float* __restrict__ gamma,
                          const float* __restrict__ beta, float invN)
{
    int j = threadIdx.x;
    float mu  = g_SUM[j] * invN;
    float var = g_SSQ[j] * invN - mu * mu;
    float a   = gamma[j] * rsqrtf(var + 1e-5f);
    g_CA[j] = a;
    g_CB[j] = beta[j] - mu * a;
}

// ---------------------------------------------------------------------------
// Link scoring
// ---------------------------------------------------------------------------
__global__ __launch_bounds__(256) void k_score(const int* __restrict__ li,
                                               int EL, float* __restrict__ out)
{
    int w    = (blockIdx.x * blockDim.x + threadIdx.x) >> 5;
    int lane = threadIdx.x & 31;
    if (w >= EL) return;
    int s = li[w];
    int t = li[EL + w];
    const float4* ps = (const float4*)(g_OUT + (size_t)s * HC);
    const float4* pt = (const float4*)(g_OUT + (size_t)t * HC);
    float acc = 0.f;
#pragma unroll
    for (int k = 0; k < 4; k++) {
        int idx = lane + 32 * k;
        float4 a4 = ps[idx];
        float4 b4 = pt[idx];
        float4 ca = *(const float4*)(g_CA + idx * 4);
        float4 cb = *(const float4*)(g_CB + idx * 4);
        float sx = fmaxf(fmaf(a4.x, ca.x, cb.x), 0.f);
        float sy = fmaxf(fmaf(a4.y, ca.y, cb.y), 0.f);
        float sz = fmaxf(fmaf(a4.z, ca.z, cb.z), 0.f);
        float sw = fmaxf(fmaf(a4.w, ca.w, cb.w), 0.f);
        float tx = fmaxf(fmaf(b4.x, ca.x, cb.x), 0.f);
        float ty = fmaxf(fmaf(b4.y, ca.y, cb.y), 0.f);
        float tz = fmaxf(fmaf(b4.z, ca.z, cb.z), 0.f);
        float tw = fmaxf(fmaf(b4.w, ca.w, cb.w), 0.f);
        acc += sx * tx + sy * ty + sz * tz + sw * tw;
    }
#pragma unroll
    for (int o = 16; o; o >>= 1) acc += __shfl_xor_sync(0xffffffffu, acc, o);
    if (lane == 0) out[w] = acc;
}

// ---------------------------------------------------------------------------
// Launch
// ---------------------------------------------------------------------------
extern "C" void kernel_launch(void* const* d_in, const int* in_sizes, int n_in,
                              void* d_out, int out_size)
{
    const float* x     = (const float*)d_in[0];
    const int*   ei    = (const int*)d_in[1];
    const int*   eli   = (const int*)d_in[2];
    const float* Wl    = (const float*)d_in[3];
    const float* Wr    = (const float*)d_in[4];
    const float* att   = (const float*)d_in[5];
    // d_in[6] = bias: cancels under BatchNorm (mean-subtracted), unused
    const float* gamma = (const float*)d_in[7];
    const float* beta  = (const float*)d_in[8];
    float* out = (float*)d_out;

    const int N  = in_sizes[0] / INCH;
    const int E  = in_sizes[1] / 2;
    const int EL = in_sizes[2] / 2;
    const int* src = ei;
    const int* dst = ei + E;
    const int nb = (N + 255) / 256;

    k_zero<<<(N + 255) / 256, 256>>>(N);

    {
        dim3 grid(8, (N + 127) / 128);
        k_gemm<<<grid, 256>>>(x, Wl, Wr, N);
    }

    k_hist<<<(E + 255) / 256, 256>>>(dst, E);
    k_scan_part<<<nb, 256>>>(N);
    k_scan_final<<<nb, 256>>>(N, nb);
    k_scatter<<<(E + 255) / 256, 256>>>(src, dst, E);

    k_edge<<<(N * 32 + 255) / 256, 256>>>(att, N);

    {
        int rows_per = 40;
        int blocks = (N + rows_per - 1) / rows_per;
        k_bn_stats<<<blocks, 512>>>(N, rows_per);
        k_bn_coef<<<1, HC>>>(gamma, beta, 1.0f / (float)N);
    }

    k_score<<<(EL * 32 + 255) / 256, 256>>>(eli, EL, out);
}

// round 7
// speedup vs baseline: 2.3169x; 1.0657x over previous
#include <cuda_runtime.h>

// ---------------------------------------------------------------------------
// Problem constants
// ---------------------------------------------------------------------------
#define NMAX   20000
#define EMAX   320000
#define HEADS  8
#define CH     64
#define HC     512
#define INCH   512
#define NB_SCAN ((NMAX + 255) / 256)

// ---------------------------------------------------------------------------
// Scratch (static device globals; no allocations allowed)
// ---------------------------------------------------------------------------
__device__ float g_XLR[(size_t)NMAX * 1024];   // [:,0:512]=x@Wl, [:,512:1024]=x@Wr
__device__ int   g_DEG[NMAX];
__device__ int   g_START[NMAX];
__device__ int   g_CURSOR[NMAX];
__device__ int   g_CSRC[EMAX];                 // CSR source-node list
__device__ int   g_PART[NB_SCAN];
__device__ float g_OUT[(size_t)NMAX * HC];
__device__ float g_SUM[HC];
__device__ float g_SSQ[HC];
__device__ float g_CA[HC];
__device__ float g_CB[HC];

// ---------------------------------------------------------------------------
// init: zero degree histogram + BN accumulators
// ---------------------------------------------------------------------------
__global__ void k_zero(int N)
{
    int i = blockIdx.x * blockDim.x + threadIdx.x;
    if (i < N) g_DEG[i] = 0;
    if (i < HC) { g_SUM[i] = 0.f; g_SSQ[i] = 0.f; }
}

// ---------------------------------------------------------------------------
// tf32 helpers
// ---------------------------------------------------------------------------
__device__ __forceinline__ float to_tf32(float f)
{
    unsigned u;
    asm("cvt.rna.tf32.f32 %0, %1;" : "=r"(u) : "f"(f));
    return __uint_as_float(u);
}

__device__ __forceinline__ void mma_tf32(float c[4], const float a[4], const float b[2])
{
    asm volatile(
        "mma.sync.aligned.m16n8k8.row.col.f32.tf32.tf32.f32 "
        "{%0,%1,%2,%3},{%4,%5,%6,%7},{%8,%9},{%0,%1,%2,%3};"
        : "+f"(c[0]), "+f"(c[1]), "+f"(c[2]), "+f"(c[3])
        : "r"(__float_as_uint(a[0])), "r"(__float_as_uint(a[1])),
          "r"(__float_as_uint(a[2])), "r"(__float_as_uint(a[3])),
          "r"(__float_as_uint(b[0])), "r"(__float_as_uint(b[1])));
}

// ---------------------------------------------------------------------------
// tf32 GEMM, double-buffered: g_XLR[M,1024] = x[M,512] @ [Wl | Wr]
// block tile 128x128, BK=16, 256 thr = 8 warps, warp tile 32x64
// ---------------------------------------------------------------------------
#define APAD 132
__global__ __launch_bounds__(256) void k_gemm(const float* __restrict__ x,
                                              const float* __restrict__ Wl,
                                              const float* __restrict__ Wr,
                                              int M)
{
    __shared__ float As[2][16][APAD];   // As[s][k][m], tf32-rounded
    __shared__ float Bs[2][16][APAD];   // Bs[s][k][n]

    const int bn   = blockIdx.x;                 // 0..7 over 1024 cols
    const int row0 = blockIdx.y * 128;
    const float* W = (bn < 4) ? Wl : Wr;
    const int col0 = (bn & 3) * 128;

    const int tid  = threadIdx.x;
    const int warp = tid >> 5;
    const int lane = tid & 31;
    const int wm   = warp >> 1;                  // 0..3
    const int wn   = warp & 1;                   // 0..1
    const int gid  = lane >> 2;                  // 0..7
    const int tig  = lane & 3;                   // 0..3

    const int a_r = tid >> 2;                    // 0..63
    const int a_c = (tid & 3) << 2;              // 0,4,8,12
    const int b_r = tid >> 5;                    // 0..7
    const int b_c = (tid & 31) << 2;             // 0..124

    float c[2][8][4];
#pragma unroll
    for (int i = 0; i < 2; i++)
#pragma unroll
        for (int j = 0; j < 8; j++)
#pragma unroll
            for (int q = 0; q < 4; q++) c[i][j][q] = 0.f;

    float4 va[2], vb[2];

    // prologue: load k0=0 tile
#pragma unroll
    for (int i = 0; i < 2; i++) {
        int gr = row0 + a_r + i * 64;
        va[i] = make_float4(0.f, 0.f, 0.f, 0.f);
        if (gr < M) va[i] = *(const float4*)(x + (size_t)gr * INCH + a_c);
        vb[i] = *(const float4*)(W + (size_t)(b_r + i * 8) * HC + col0 + b_c);
    }
#pragma unroll
    for (int i = 0; i < 2; i++) {
        int r = a_r + i * 64;
        As[0][a_c + 0][r] = to_tf32(va[i].x);
        As[0][a_c + 1][r] = to_tf32(va[i].y);
        As[0][a_c + 2][r] = to_tf32(va[i].z);
        As[0][a_c + 3][r] = to_tf32(va[i].w);
        int br = b_r + i * 8;
        float4 t = make_float4(to_tf32(vb[i].x), to_tf32(vb[i].y),
                               to_tf32(vb[i].z), to_tf32(vb[i].w));
        *(float4*)&Bs[0][br][b_c] = t;
    }
    __syncthreads();

    int buf = 0;
    for (int k0 = 0; k0 < INCH; k0 += 16) {
        const bool last = (k0 + 16 >= INCH);
        if (!last) {
#pragma unroll
            for (int i = 0; i < 2; i++) {
                int gr = row0 + a_r + i * 64;
                va[i] = make_float4(0.f, 0.f, 0.f, 0.f);
                if (gr < M)
                    va[i] = *(const float4*)(x + (size_t)gr * INCH + k0 + 16 + a_c);
                vb[i] = *(const float4*)(W + (size_t)(k0 + 16 + b_r + i * 8) * HC +
                                         col0 + b_c);
            }
        }

#pragma unroll
        for (int ks = 0; ks < 16; ks += 8) {
            float a[2][4];
#pragma unroll
            for (int mt = 0; mt < 2; mt++) {
                int mr = wm * 32 + mt * 16 + gid;
                a[mt][0] = As[buf][ks + tig][mr];
                a[mt][1] = As[buf][ks + tig][mr + 8];
                a[mt][2] = As[buf][ks + tig + 4][mr];
                a[mt][3] = As[buf][ks + tig + 4][mr + 8];
            }
            float b[8][2];
#pragma unroll
            for (int nt = 0; nt < 8; nt++) {
                int nc = wn * 64 + nt * 8 + gid;
                b[nt][0] = Bs[buf][ks + tig][nc];
                b[nt][1] = Bs[buf][ks + tig + 4][nc];
            }
#pragma unroll
            for (int mt = 0; mt < 2; mt++)
#pragma unroll
                for (int nt = 0; nt < 8; nt++)
                    mma_tf32(c[mt][nt], a[mt], b[nt]);
        }

        if (!last) {
            int nb = buf ^ 1;
#pragma unroll
            for (int i = 0; i < 2; i++) {
                int r = a_r + i * 64;
                As[nb][a_c + 0][r] = to_tf32(va[i].x);
                As[nb][a_c + 1][r] = to_tf32(va[i].y);
                As[nb][a_c + 2][r] = to_tf32(va[i].z);
                As[nb][a_c + 3][r] = to_tf32(va[i].w);
                int br = b_r + i * 8;
                float4 t = make_float4(to_tf32(vb[i].x), to_tf32(vb[i].y),
                                       to_tf32(vb[i].z), to_tf32(vb[i].w));
                *(float4*)&Bs[nb][br][b_c] = t;
            }
            __syncthreads();
            buf = nb;
        }
    }

    // store C
#pragma unroll
    for (int mt = 0; mt < 2; mt++) {
#pragma unroll
        for (int nt = 0; nt < 8; nt++) {
            int r   = row0 + wm * 32 + mt * 16 + gid;
            int col = bn * 128 + wn * 64 + nt * 8 + 2 * tig;
            if (r < M)
                *(float2*)(g_XLR + (size_t)r * 1024 + col) =
                    make_float2(c[mt][nt][0], c[mt][nt][1]);
            if (r + 8 < M)
                *(float2*)(g_XLR + (size_t)(r + 8) * 1024 + col) =
                    make_float2(c[mt][nt][2], c[mt][nt][3]);
        }
    }
}

// ---------------------------------------------------------------------------
// CSR build: histogram -> parallel scan -> scatter
// ---------------------------------------------------------------------------
__global__ void k_hist(const int* __restrict__ dst, int E)
{
    int e = blockIdx.x * blockDim.x + threadIdx.x;
    if (e < E) atomicAdd(&g_DEG[dst[e]], 1);
}

__global__ __launch_bounds__(256) void k_scan_part(int N)
{
    __shared__ int wsum[8];
    int i = blockIdx.x * 256 + threadIdx.x;
    int v = (i < N) ? g_DEG[i] : 0;
    int lane = threadIdx.x & 31, wid = threadIdx.x >> 5;
#pragma unroll
    for (int o = 16; o; o >>= 1) v += __shfl_xor_sync(0xffffffffu, v, o);
    if (lane == 0) wsum[wid] = v;
    __syncthreads();
    if (threadIdx.x == 0) {
        int s = 0;
#pragma unroll
        for (int w2 = 0; w2 < 8; w2++) s += wsum[w2];
        g_PART[blockIdx.x] = s;
    }
}

__global__ __launch_bounds__(256) void k_scan_final(int N, int nb)
{
    __shared__ int wsum[8];
    __shared__ int wscan[8];
    __shared__ int sh_base;
    const int b = blockIdx.x;
    const int t = threadIdx.x;
    const int lane = t & 31, wid = t >> 5;

    int ps = 0;
    for (int i = t; i < b; i += 256) ps += g_PART[i];
#pragma unroll
    for (int o = 16; o; o >>= 1) ps += __shfl_xor_sync(0xffffffffu, ps, o);
    if (lane == 0) wsum[wid] = ps;
    __syncthreads();
    if (t == 0) {
        int s = 0;
#pragma unroll
        for (int w2 = 0; w2 < 8; w2++) s += wsum[w2];
        sh_base = s;
    }
    __syncthreads();
    const int base = sh_base;

    int i = b * 256 + t;
    int v = (i < N) ? g_DEG[i] : 0;
    int xinc = v;
#pragma unroll
    for (int o = 1; o < 32; o <<= 1) {
        int y = __shfl_up_sync(0xffffffffu, xinc, o);
        if (lane >= o) xinc += y;
    }
    if (lane == 31) wscan[wid] = xinc;
    __syncthreads();
    int off = 0;
#pragma unroll
    for (int w2 = 0; w2 < 8; w2++) off += (w2 < wid) ? wscan[w2] : 0;
    if (i < N) {
        int e = base + off + xinc - v;
        g_START[i]  = e;
        g_CURSOR[i] = e;
    }
}

__global__ void k_scatter(const int* __restrict__ src,
                          const int* __restrict__ dst, int E)
{
    int e = blockIdx.x * blockDim.x + threadIdx.x;
    if (e >= E) return;
    int d   = dst[e];
    int pos = atomicAdd(&g_CURSOR[d], 1);
    g_CSRC[pos] = src[e];
}

// ---------------------------------------------------------------------------
// Fused GATv2 with ONLINE softmax, 2 edges per iteration for MLP.
// One warp per destination node. Lane owns channels c = lane*4 + 128*k.
// After the 16-lane butterfly, lane holds the logit of head 2k+(lane>>4).
// ---------------------------------------------------------------------------
__global__ __launch_bounds__(256) void k_edge(const float* __restrict__ att, int N)
{
    int w    = (blockIdx.x * blockDim.x + threadIdx.x) >> 5;
    int lane = threadIdx.x & 31;
    if (w >= N) return;
    const int d     = w;
    const int start = g_START[d];
    const int deg   = g_DEG[d];
    const int c0    = lane * 4;

    float4 attv[4], xrv[4];
#pragma unroll
    for (int k = 0; k < 4; k++) {
        attv[k] = __ldg((const float4*)(att + c0 + 128 * k));
        xrv[k]  = *(const float4*)(g_XLR + (size_t)d * 1024 + 512 + c0 + 128 * k);
    }

    float  m[4], dnm[4];
    float4 acc[4];
#pragma unroll
    for (int k = 0; k < 4; k++) {
        m[k] = -1e30f; dnm[k] = 0.f;
        acc[k] = make_float4(0.f, 0.f, 0.f, 0.f);
    }

    int j = 0;
    for (; j + 2 <= deg; j += 2) {
        int s0 = g_CSRC[start + j];
        int s1 = g_CSRC[start + j + 1];
        const float* xl0 = g_XLR + (size_t)s0 * 1024;
        const float* xl1 = g_XLR + (size_t)s1 * 1024;
        float4 v[2][4];
        float  p[2][4];
        // all 8 loads in flight before any math
#pragma unroll
        for (int k = 0; k < 4; k++) v[0][k] = *(const float4*)(xl0 + c0 + 128 * k);
#pragma unroll
        for (int k = 0; k < 4; k++) v[1][k] = *(const float4*)(xl1 + c0 + 128 * k);

#pragma unroll
        for (int e2 = 0; e2 < 2; e2++) {
#pragma unroll
            for (int k = 0; k < 4; k++) {
                float tx = v[e2][k].x + xrv[k].x, ty = v[e2][k].y + xrv[k].y;
                float tz = v[e2][k].z + xrv[k].z, tw = v[e2][k].w + xrv[k].w;
                tx = (tx > 0.f) ? tx : 0.2f * tx;
                ty = (ty > 0.f) ? ty : 0.2f * ty;
                tz = (tz > 0.f) ? tz : 0.2f * tz;
                tw = (tw > 0.f) ? tw : 0.2f * tw;
                p[e2][k] = tx * attv[k].x + ty * attv[k].y +
                           tz * attv[k].z + tw * attv[k].w;
            }
        }
        // two independent butterfly chains (interleaved by scheduler)
#pragma unroll
        for (int e2 = 0; e2 < 2; e2++)
#pragma unroll
            for (int k = 0; k < 4; k++) {
                p[e2][k] += __shfl_xor_sync(0xffffffffu, p[e2][k], 1);
                p[e2][k] += __shfl_xor_sync(0xffffffffu, p[e2][k], 2);
                p[e2][k] += __shfl_xor_sync(0xffffffffu, p[e2][k], 4);
                p[e2][k] += __shfl_xor_sync(0xffffffffu, p[e2][k], 8);
            }
        // sequential online updates
#pragma unroll
        for (int e2 = 0; e2 < 2; e2++) {
#pragma unroll
            for (int k = 0; k < 4; k++) {
                float mn = fmaxf(m[k], p[e2][k]);
                float r  = __expf(m[k] - mn);
                float e  = __expf(p[e2][k] - mn);
                dnm[k]   = fmaf(dnm[k], r, e);
                acc[k].x = fmaf(acc[k].x, r, e * v[e2][k].x);
                acc[k].y = fmaf(acc[k].y, r, e * v[e2][k].y);
                acc[k].z = fmaf(acc[k].z, r, e * v[e2][k].z);
                acc[k].w = fmaf(acc[k].w, r, e * v[e2][k].w);
                m[k] = mn;
            }
        }
    }
    // tail edge
    if (j < deg) {
        int s = g_CSRC[start + j];
        const float* xl = g_XLR + (size_t)s * 1024;
        float4 v[4];
        float  p[4];
#pragma unroll
        for (int k = 0; k < 4; k++) {
            v[k] = *(const float4*)(xl + c0 + 128 * k);
            float tx = v[k].x + xrv[k].x, ty = v[k].y + xrv[k].y;
            float tz = v[k].z + xrv[k].z, tw = v[k].w + xrv[k].w;
            tx = (tx > 0.f) ? tx : 0.2f * tx;
            ty = (ty > 0.f) ? ty : 0.2f * ty;
            tz = (tz > 0.f) ? tz : 0.2f * tz;
            tw = (tw > 0.f) ? tw : 0.2f * tw;
            p[k] = tx * attv[k].x + ty * attv[k].y + tz * attv[k].z + tw * attv[k].w;
        }
#pragma unroll
        for (int k = 0; k < 4; k++) {
            p[k] += __shfl_xor_sync(0xffffffffu, p[k], 1);
            p[k] += __shfl_xor_sync(0xffffffffu, p[k], 2);
            p[k] += __shfl_xor_sync(0xffffffffu, p[k], 4);
            p[k] += __shfl_xor_sync(0xffffffffu, p[k], 8);
        }
#pragma unroll
        for (int k = 0; k < 4; k++) {
            float mn = fmaxf(m[k], p[k]);
            float r  = __expf(m[k] - mn);
            float e  = __expf(p[k] - mn);
            dnm[k]   = fmaf(dnm[k], r, e);
            acc[k].x = fmaf(acc[k].x, r, e * v[k].x);
            acc[k].y = fmaf(acc[k].y, r, e * v[k].y);
            acc[k].z = fmaf(acc[k].z, r, e * v[k].z);
            acc[k].w = fmaf(acc[k].w, r, e * v[k].w);
            m[k] = mn;
        }
    }

#pragma unroll
    for (int k = 0; k < 4; k++) {
        float inv = 1.0f / (dnm[k] + 1e-16f);
        float4 o = make_float4(acc[k].x * inv, acc[k].y * inv,
                               acc[k].z * inv, acc[k].w * inv);
        *(float4*)(g_OUT + (size_t)d * HC + c0 + 128 * k) = o;
    }
}

// ---------------------------------------------------------------------------
// BatchNorm stats / coefficients
// ---------------------------------------------------------------------------
__global__ __launch_bounds__(512) void k_bn_stats(int n_nodes, int rows_per)
{
    int j  = threadIdx.x;
    int r0 = blockIdx.x * rows_per;
    int r1 = min(r0 + rows_per, n_nodes);
    float s = 0.f, q = 0.f;
    for (int r = r0; r < r1; r++) {
        float v = g_OUT[(size_t)r * HC + j];
        s += v;
        q = fmaf(v, v, q);
    }
    atomicAdd(&g_SUM[j], s);
    atomicAdd(&g_SSQ[j], q);
}

__global__ void k_bn_coef(const float* __restrict__ gamma,
                          const float* __restrict__ beta, float invN)
{
    int j = threadIdx.x;
    float mu  = g_SUM[j] * invN;
    float var = g_SSQ[j] * invN - mu * mu;
    float a   = gamma[j] * rsqrtf(var + 1e-5f);
    g_CA[j] = a;
    g_CB[j] = beta[j] - mu * a;
}

// ---------------------------------------------------------------------------
// Link scoring: 2 label-edges per warp for MLP
// ---------------------------------------------------------------------------
__global__ __launch_bounds__(256) void k_score(const int* __restrict__ li,
                                               int EL, float* __restrict__ out)
{
    int w    = (blockIdx.x * blockDim.x + threadIdx.x) >> 5;
    int lane = threadIdx.x & 31;
    int e0 = w * 2;
    if (e0 >= EL) return;
    int ne = (e0 + 1 < EL) ? 2 : 1;

    float accv[2] = {0.f, 0.f};
#pragma unroll
    for (int q = 0; q < 2; q++) {
        if (q >= ne) break;
        int s = li[e0 + q];
        int t = li[EL + e0 + q];
        const float4* ps = (const float4*)(g_OUT + (size_t)s * HC);
        const float4* pt = (const float4*)(g_OUT + (size_t)t * HC);
        float acc = 0.f;
#pragma unroll
        for (int k = 0; k < 4; k++) {
            int idx = lane + 32 * k;
            float4 a4 = ps[idx];
            float4 b4 = pt[idx];
            float4 ca = *(const float4*)(g_CA + idx * 4);
            float4 cb = *(const float4*)(g_CB + idx * 4);
            float sx = fmaxf(fmaf(a4.x, ca.x, cb.x), 0.f);
            float sy = fmaxf(fmaf(a4.y, ca.y, cb.y), 0.f);
            float sz = fmaxf(fmaf(a4.z, ca.z, cb.z), 0.f);
            float sw = fmaxf(fmaf(a4.w, ca.w, cb.w), 0.f);
            float tx = fmaxf(fmaf(b4.x, ca.x, cb.x), 0.f);
            float ty = fmaxf(fmaf(b4.y, ca.y, cb.y), 0.f);
            float tz = fmaxf(fmaf(b4.z, ca.z, cb.z), 0.f);
            float tw = fmaxf(fmaf(b4.w, ca.w, cb.w), 0.f);
            acc += sx * tx + sy * ty + sz * tz + sw * tw;
        }
        accv[q] = acc;
    }
#pragma unroll
    for (int q = 0; q < 2; q++) {
#pragma unroll
        for (int o = 16; o; o >>= 1)
            accv[q] += __shfl_xor_sync(0xffffffffu, accv[q], o);
    }
    if (lane == 0) {
        out[e0] = accv[0];
        if (ne == 2) out[e0 + 1] = accv[1];
    }
}

// ---------------------------------------------------------------------------
// Launch
// ---------------------------------------------------------------------------
extern "C" void kernel_launch(void* const* d_in, const int* in_sizes, int n_in,
                              void* d_out, int out_size)
{
    const float* x     = (const float*)d_in[0];
    const int*   ei    = (const int*)d_in[1];
    const int*   eli   = (const int*)d_in[2];
    const float* Wl    = (const float*)d_in[3];
    const float* Wr    = (const float*)d_in[4];
    const float* att   = (const float*)d_in[5];
    // d_in[6] = bias: cancels under BatchNorm (mean-subtracted), unused
    const float* gamma = (const float*)d_in[7];
    const float* beta  = (const float*)d_in[8];
    float* out = (float*)d_out;

    const int N  = in_sizes[0] / INCH;
    const int E  = in_sizes[1] / 2;
    const int EL = in_sizes[2] / 2;
    const int* src = ei;
    const int* dst = ei + E;
    const int nb = (N + 255) / 256;

    k_zero<<<(N + 255) / 256, 256>>>(N);

    {
        dim3 grid(8, (N + 127) / 128);
        k_gemm<<<grid, 256>>>(x, Wl, Wr, N);
    }

    k_hist<<<(E + 255) / 256, 256>>>(dst, E);
    k_scan_part<<<nb, 256>>>(N);
    k_scan_final<<<nb, 256>>>(N, nb);
    k_scatter<<<(E + 255) / 256, 256>>>(src, dst, E);

    k_edge<<<(N * 32 + 255) / 256, 256>>>(att, N);

    {
        int rows_per = 40;
        int blocks = (N + rows_per - 1) / rows_per;
        k_bn_stats<<<blocks, 512>>>(N, rows_per);
        k_bn_coef<<<1, HC>>>(gamma, beta, 1.0f / (float)N);
    }

    {
        int warps = (EL + 1) / 2;
        k_score<<<(warps * 32 + 255) / 256, 256>>>(eli, EL, out);
    }
}

// round 8
// speedup vs baseline: 2.9033x; 1.2531x over previous
#include <cuda_runtime.h>
#include <cuda_bf16.h>

// ---------------------------------------------------------------------------
// Problem constants
// ---------------------------------------------------------------------------
#define NMAX   20000
#define EMAX   320000
#define HEADS  8
#define CH     64
#define HC     512
#define INCH   512
#define NB_SCAN ((NMAX + 255) / 256)

// ---------------------------------------------------------------------------
// Scratch (static device globals; no allocations allowed)
// ---------------------------------------------------------------------------
__device__ float g_XLR[(size_t)NMAX * 1024];   // [:,0:512]=x@Wl, [:,512:1024]=x@Wr
__device__ int   g_DEG[NMAX];
__device__ int   g_START[NMAX];
__device__ int   g_CURSOR[NMAX];
__device__ int   g_CSRC[EMAX];                 // CSR source-node list
__device__ int   g_PART[NB_SCAN];
__device__ float g_OUT[(size_t)NMAX * HC];
__device__ float g_SUM[HC];
__device__ float g_SSQ[HC];
__device__ float g_CA[HC];
__device__ float g_CB[HC];

// ---------------------------------------------------------------------------
// init: zero degree histogram + BN accumulators
// ---------------------------------------------------------------------------
__global__ void k_zero(int N)
{
    int i = blockIdx.x * blockDim.x + threadIdx.x;
    if (i < N) g_DEG[i] = 0;
    if (i < HC) { g_SUM[i] = 0.f; g_SSQ[i] = 0.f; }
}

// ---------------------------------------------------------------------------
// bf16 helpers
// ---------------------------------------------------------------------------
// pack two floats into bf16x2: lo = first arg, hi = second arg
__device__ __forceinline__ unsigned pack_bf16(float lo, float hi)
{
    unsigned r;
    asm("cvt.rn.bf16x2.f32 %0, %1, %2;" : "=r"(r) : "f"(hi), "f"(lo));
    return r;
}

__device__ __forceinline__ void mma_bf16(float c[4], const unsigned a[4],
                                         const unsigned b[2])
{
    asm volatile(
        "mma.sync.aligned.m16n8k16.row.col.f32.bf16.bf16.f32 "
        "{%0,%1,%2,%3},{%4,%5,%6,%7},{%8,%9},{%0,%1,%2,%3};"
        : "+f"(c[0]), "+f"(c[1]), "+f"(c[2]), "+f"(c[3])
        : "r"(a[0]), "r"(a[1]), "r"(a[2]), "r"(a[3]),
          "r"(b[0]), "r"(b[1]));
}

// ---------------------------------------------------------------------------
// bf16 GEMM, double-buffered: g_XLR[M,1024] = x[M,512] @ [Wl | Wr]
// block tile 128x128, BK=16, 256 thr = 8 warps, warp tile 32x64.
// smem tiles are k-pair packed: As2[kk][m] = {bf16(k=2kk), bf16(k=2kk+1)}
// so each mma fragment register is a single conflict-free LDS.32.
// ---------------------------------------------------------------------------
#define KKPAD 132
__global__ __launch_bounds__(256) void k_gemm(const float* __restrict__ x,
                                              const float* __restrict__ Wl,
                                              const float* __restrict__ Wr,
                                              int M)
{
    __shared__ unsigned As2[2][8][KKPAD];   // [stage][kk][m]
    __shared__ unsigned Bs2[2][8][KKPAD];   // [stage][kk][n]

    const int bn   = blockIdx.x;                 // 0..7 over 1024 cols
    const int row0 = blockIdx.y * 128;
    const float* W = (bn < 4) ? Wl : Wr;
    const int col0 = (bn & 3) * 128;

    const int tid  = threadIdx.x;
    const int warp = tid >> 5;
    const int lane = tid & 31;
    const int wm   = warp >> 1;                  // 0..3
    const int wn   = warp & 1;                   // 0..1
    const int gid  = lane >> 2;                  // 0..7
    const int tig  = lane & 3;                   // 0..3

    // A staging: thread handles rows (tid>>2)+{0,64}, k-chunk (tid&3)*4
    const int a_r = tid >> 2;                    // 0..63
    const int a_c = (tid & 3) << 2;              // 0,4,8,12
    // B staging: thread handles kk = tid>>5, n4 = (tid&31)*4
    const int b_kk = tid >> 5;                   // 0..7
    const int b_n  = (tid & 31) << 2;            // 0..124

    float c[2][8][4];
#pragma unroll
    for (int i = 0; i < 2; i++)
#pragma unroll
        for (int j = 0; j < 8; j++)
#pragma unroll
            for (int q = 0; q < 4; q++) c[i][j][q] = 0.f;

    float4 va[2];        // A: rows a_r, a_r+64 at k-chunk a_c
    float4 vb0, vb1;     // B: rows 2*b_kk, 2*b_kk+1 at cols b_n..b_n+3

    // ---- prologue: global load k0=0 ----
#pragma unroll
    for (int i = 0; i < 2; i++) {
        int gr = row0 + a_r + i * 64;
        va[i] = make_float4(0.f, 0.f, 0.f, 0.f);
        if (gr < M) va[i] = *(const float4*)(x + (size_t)gr * INCH + a_c);
    }
    vb0 = *(const float4*)(W + (size_t)(2 * b_kk) * HC + col0 + b_n);
    vb1 = *(const float4*)(W + (size_t)(2 * b_kk + 1) * HC + col0 + b_n);

    // stage 0 store
#pragma unroll
    for (int i = 0; i < 2; i++) {
        int r = a_r + i * 64;
        As2[0][(a_c >> 1) + 0][r] = pack_bf16(va[i].x, va[i].y);
        As2[0][(a_c >> 1) + 1][r] = pack_bf16(va[i].z, va[i].w);
    }
    {
        uint4 t;
        t.x = pack_bf16(vb0.x, vb1.x);
        t.y = pack_bf16(vb0.y, vb1.y);
        t.z = pack_bf16(vb0.z, vb1.z);
        t.w = pack_bf16(vb0.w, vb1.w);
        *(uint4*)&Bs2[0][b_kk][b_n] = t;
    }
    __syncthreads();

    int buf = 0;
    for (int k0 = 0; k0 < INCH; k0 += 16) {
        const bool last = (k0 + 16 >= INCH);
        if (!last) {
#pragma unroll
            for (int i = 0; i < 2; i++) {
                int gr = row0 + a_r + i * 64;
                va[i] = make_float4(0.f, 0.f, 0.f, 0.f);
                if (gr < M)
                    va[i] = *(const float4*)(x + (size_t)gr * INCH + k0 + 16 + a_c);
            }
            vb0 = *(const float4*)(W + (size_t)(k0 + 16 + 2 * b_kk) * HC + col0 + b_n);
            vb1 = *(const float4*)(W + (size_t)(k0 + 16 + 2 * b_kk + 1) * HC + col0 + b_n);
        }

        // ---- compute on current stage: one k16 mma per (mt,nt) ----
        {
            unsigned a[2][4];
#pragma unroll
            for (int mt = 0; mt < 2; mt++) {
                int mr = wm * 32 + mt * 16 + gid;
                a[mt][0] = As2[buf][tig][mr];
                a[mt][1] = As2[buf][tig][mr + 8];
                a[mt][2] = As2[buf][tig + 4][mr];
                a[mt][3] = As2[buf][tig + 4][mr + 8];
            }
            unsigned b[8][2];
#pragma unroll
            for (int nt = 0; nt < 8; nt++) {
                int nc = wn * 64 + nt * 8 + gid;
                b[nt][0] = Bs2[buf][tig][nc];
                b[nt][1] = Bs2[buf][tig + 4][nc];
            }
#pragma unroll
            for (int mt = 0; mt < 2; mt++)
#pragma unroll
                for (int nt = 0; nt < 8; nt++)
                    mma_bf16(c[mt][nt], a[mt], b[nt]);
        }

        if (!last) {
            int nb = buf ^ 1;
#pragma unroll
            for (int i = 0; i < 2; i++) {
                int r = a_r + i * 64;
                As2[nb][(a_c >> 1) + 0][r] = pack_bf16(va[i].x, va[i].y);
                As2[nb][(a_c >> 1) + 1][r] = pack_bf16(va[i].z, va[i].w);
            }
            uint4 t;
            t.x = pack_bf16(vb0.x, vb1.x);
            t.y = pack_bf16(vb0.y, vb1.y);
            t.z = pack_bf16(vb0.z, vb1.z);
            t.w = pack_bf16(vb0.w, vb1.w);
            *(uint4*)&Bs2[nb][b_kk][b_n] = t;
            __syncthreads();
            buf = nb;
        }
    }

    // ---- store C ----
#pragma unroll
    for (int mt = 0; mt < 2; mt++) {
#pragma unroll
        for (int nt = 0; nt < 8; nt++) {
            int r   = row0 + wm * 32 + mt * 16 + gid;
            int col = bn * 128 + wn * 64 + nt * 8 + 2 * tig;
            if (r < M)
                *(float2*)(g_XLR + (size_t)r * 1024 + col) =
                    make_float2(c[mt][nt][0], c[mt][nt][1]);
            if (r + 8 < M)
                *(float2*)(g_XLR + (size_t)(r + 8) * 1024 + col) =
                    make_float2(c[mt][nt][2], c[mt][nt][3]);
        }
    }
}

// ---------------------------------------------------------------------------
// CSR build: histogram -> parallel scan -> scatter
// ---------------------------------------------------------------------------
__global__ void k_hist(const int* __restrict__ dst, int E)
{
    int e = blockIdx.x * blockDim.x + threadIdx.x;
    if (e < E) atomicAdd(&g_DEG[dst[e]], 1);
}

__global__ __launch_bounds__(256) void k_scan_part(int N)
{
    __shared__ int wsum[8];
    int i = blockIdx.x * 256 + threadIdx.x;
    int v = (i < N) ? g_DEG[i] : 0;
    int lane = threadIdx.x & 31, wid = threadIdx.x >> 5;
#pragma unroll
    for (int o = 16; o; o >>= 1) v += __shfl_xor_sync(0xffffffffu, v, o);
    if (lane == 0) wsum[wid] = v;
    __syncthreads();
    if (threadIdx.x == 0) {
        int s = 0;
#pragma unroll
        for (int w2 = 0; w2 < 8; w2++) s += wsum[w2];
        g_PART[blockIdx.x] = s;
    }
}

__global__ __launch_bounds__(256) void k_scan_final(int N, int nb)
{
    __shared__ int wsum[8];
    __shared__ int wscan[8];
    __shared__ int sh_base;
    const int b = blockIdx.x;
    const int t = threadIdx.x;
    const int lane = t & 31, wid = t >> 5;

    int ps = 0;
    for (int i = t; i < b; i += 256) ps += g_PART[i];
#pragma unroll
    for (int o = 16; o; o >>= 1) ps += __shfl_xor_sync(0xffffffffu, ps, o);
    if (lane == 0) wsum[wid] = ps;
    __syncthreads();
    if (t == 0) {
        int s = 0;
#pragma unroll
        for (int w2 = 0; w2 < 8; w2++) s += wsum[w2];
        sh_base = s;
    }
    __syncthreads();
    const int base = sh_base;

    int i = b * 256 + t;
    int v = (i < N) ? g_DEG[i] : 0;
    int xinc = v;
#pragma unroll
    for (int o = 1; o < 32; o <<= 1) {
        int y = __shfl_up_sync(0xffffffffu, xinc, o);
        if (lane >= o) xinc += y;
    }
    if (lane == 31) wscan[wid] = xinc;
    __syncthreads();
    int off = 0;
#pragma unroll
    for (int w2 = 0; w2 < 8; w2++) off += (w2 < wid) ? wscan[w2] : 0;
    if (i < N) {
        int e = base + off + xinc - v;
        g_START[i]  = e;
        g_CURSOR[i] = e;
    }
}

__global__ void k_scatter(const int* __restrict__ src,
                          const int* __restrict__ dst, int E)
{
    int e = blockIdx.x * blockDim.x + threadIdx.x;
    if (e >= E) return;
    int d   = dst[e];
    int pos = atomicAdd(&g_CURSOR[d], 1);
    g_CSRC[pos] = src[e];
}

// ---------------------------------------------------------------------------
// Fused GATv2 with ONLINE softmax, 2 edges per iteration for MLP.
// One warp per destination node. Lane owns channels c = lane*4 + 128*k.
// After the 16-lane butterfly, lane holds the logit of head 2k+(lane>>4).
// ---------------------------------------------------------------------------
__global__ __launch_bounds__(256) void k_edge(const float* __restrict__ att, int N)
{
    int w    = (blockIdx.x * blockDim.x + threadIdx.x) >> 5;
    int lane = threadIdx.x & 31;
    if (w >= N) return;
    const int d     = w;
    const int start = g_START[d];
    const int deg   = g_DEG[d];
    const int c0    = lane * 4;

    float4 attv[4], xrv[4];
#pragma unroll
    for (int k = 0; k < 4; k++) {
        attv[k] = __ldg((const float4*)(att + c0 + 128 * k));
        xrv[k]  = *(const float4*)(g_XLR + (size_t)d * 1024 + 512 + c0 + 128 * k);
    }

    float  m[4], dnm[4];
    float4 acc[4];
#pragma unroll
    for (int k = 0; k < 4; k++) {
        m[k] = -1e30f; dnm[k] = 0.f;
        acc[k] = make_float4(0.f, 0.f, 0.f, 0.f);
    }

    int j = 0;
    for (; j + 2 <= deg; j += 2) {
        int s0 = g_CSRC[start + j];
        int s1 = g_CSRC[start + j + 1];
        const float* xl0 = g_XLR + (size_t)s0 * 1024;
        const float* xl1 = g_XLR + (size_t)s1 * 1024;
        float4 v[2][4];
        float  p[2][4];
#pragma unroll
        for (int k = 0; k < 4; k++) v[0][k] = *(const float4*)(xl0 + c0 + 128 * k);
#pragma unroll
        for (int k = 0; k < 4; k++) v[1][k] = *(const float4*)(xl1 + c0 + 128 * k);

#pragma unroll
        for (int e2 = 0; e2 < 2; e2++) {
#pragma unroll
            for (int k = 0; k < 4; k++) {
                float tx = v[e2][k].x + xrv[k].x, ty = v[e2][k].y + xrv[k].y;
                float tz = v[e2][k].z + xrv[k].z, tw = v[e2][k].w + xrv[k].w;
                tx = (tx > 0.f) ? tx : 0.2f * tx;
                ty = (ty > 0.f) ? ty : 0.2f * ty;
                tz = (tz > 0.f) ? tz : 0.2f * tz;
                tw = (tw > 0.f) ? tw : 0.2f * tw;
                p[e2][k] = tx * attv[k].x + ty * attv[k].y +
                           tz * attv[k].z + tw * attv[k].w;
            }
        }
#pragma unroll
        for (int e2 = 0; e2 < 2; e2++)
#pragma unroll
            for (int k = 0; k < 4; k++) {
                p[e2][k] += __shfl_xor_sync(0xffffffffu, p[e2][k], 1);
                p[e2][k] += __shfl_xor_sync(0xffffffffu, p[e2][k], 2);
                p[e2][k] += __shfl_xor_sync(0xffffffffu, p[e2][k], 4);
                p[e2][k] += __shfl_xor_sync(0xffffffffu, p[e2][k], 8);
            }
#pragma unroll
        for (int e2 = 0; e2 < 2; e2++) {
#pragma unroll
            for (int k = 0; k < 4; k++) {
                float mn = fmaxf(m[k], p[e2][k]);
                float r  = __expf(m[k] - mn);
                float e  = __expf(p[e2][k] - mn);
                dnm[k]   = fmaf(dnm[k], r, e);
                acc[k].x = fmaf(acc[k].x, r, e * v[e2][k].x);
                acc[k].y = fmaf(acc[k].y, r, e * v[e2][k].y);
                acc[k].z = fmaf(acc[k].z, r, e * v[e2][k].z);
                acc[k].w = fmaf(acc[k].w, r, e * v[e2][k].w);
                m[k] = mn;
            }
        }
    }
    if (j < deg) {
        int s = g_CSRC[start + j];
        const float* xl = g_XLR + (size_t)s * 1024;
        float4 v[4];
        float  p[4];
#pragma unroll
        for (int k = 0; k < 4; k++) {
            v[k] = *(const float4*)(xl + c0 + 128 * k);
            float tx = v[k].x + xrv[k].x, ty = v[k].y + xrv[k].y;
            float tz = v[k].z + xrv[k].z, tw = v[k].w + xrv[k].w;
            tx = (tx > 0.f) ? tx : 0.2f * tx;
            ty = (ty > 0.f) ? ty : 0.2f * ty;
            tz = (tz > 0.f) ? tz : 0.2f * tz;
            tw = (tw > 0.f) ? tw : 0.2f * tw;
            p[k] = tx * attv[k].x + ty * attv[k].y + tz * attv[k].z + tw * attv[k].w;
        }
#pragma unroll
        for (int k = 0; k < 4; k++) {
            p[k] += __shfl_xor_sync(0xffffffffu, p[k], 1);
            p[k] += __shfl_xor_sync(0xffffffffu, p[k], 2);
            p[k] += __shfl_xor_sync(0xffffffffu, p[k], 4);
            p[k] += __shfl_xor_sync(0xffffffffu, p[k], 8);
        }
#pragma unroll
        for (int k = 0; k < 4; k++) {
            float mn = fmaxf(m[k], p[k]);
            float r  = __expf(m[k] - mn);
            float e  = __expf(p[k] - mn);
            dnm[k]   = fmaf(dnm[k], r, e);
            acc[k].x = fmaf(acc[k].x, r, e * v[k].x);
            acc[k].y = fmaf(acc[k].y, r, e * v[k].y);
            acc[k].z = fmaf(acc[k].z, r, e * v[k].z);
            acc[k].w = fmaf(acc[k].w, r, e * v[k].w);
            m[k] = mn;
        }
    }

#pragma unroll
    for (int k = 0; k < 4; k++) {
        float inv = 1.0f / (dnm[k] + 1e-16f);
        float4 o = make_float4(acc[k].x * inv, acc[k].y * inv,
                               acc[k].z * inv, acc[k].w * inv);
        *(float4*)(g_OUT + (size_t)d * HC + c0 + 128 * k) = o;
    }
}

// ---------------------------------------------------------------------------
// BatchNorm stats / coefficients
// ---------------------------------------------------------------------------
__global__ __launch_bounds__(512) void k_bn_stats(int n_nodes, int rows_per)
{
    int j  = threadIdx.x;
    int r0 = blockIdx.x * rows_per;
    int r1 = min(r0 + rows_per, n_nodes);
    float s = 0.f, q = 0.f;
    for (int r = r0; r < r1; r++) {
        float v = g_OUT[(size_t)r * HC + j];
        s += v;
        q = fmaf(v, v, q);
    }
    atomicAdd(&g_SUM[j], s);
    atomicAdd(&g_SSQ[j], q);
}

__global__ void k_bn_coef(const float* __restrict__ gamma,
                          const float* __restrict__ beta, float invN)
{
    int j = threadIdx.x;
    float mu  = g_SUM[j] * invN;
    float var = g_SSQ[j] * invN - mu * mu;
    float a   = gamma[j] * rsqrtf(var + 1e-5f);
    g_CA[j] = a;
    g_CB[j] = beta[j] - mu * a;
}

// ---------------------------------------------------------------------------
// Link scoring: 2 label-edges per warp for MLP
// ---------------------------------------------------------------------------
__global__ __launch_bounds__(256) void k_score(const int* __restrict__ li,
                                               int EL, float* __restrict__ out)
{
    int w    = (blockIdx.x * blockDim.x + threadIdx.x) >> 5;
    int lane = threadIdx.x & 31;
    int e0 = w * 2;
    if (e0 >= EL) return;
    int ne = (e0 + 1 < EL) ? 2 : 1;

    float accv[2] = {0.f, 0.f};
#pragma unroll
    for (int q = 0; q < 2; q++) {
        if (q >= ne) break;
        int s = li[e0 + q];
        int t = li[EL + e0 + q];
        const float4* ps = (const float4*)(g_OUT + (size_t)s * HC);
        const float4* pt = (const float4*)(g_OUT + (size_t)t * HC);
        float acc = 0.f;
#pragma unroll
        for (int k = 0; k < 4; k++) {
            int idx = lane + 32 * k;
            float4 a4 = ps[idx];
            float4 b4 = pt[idx];
            float4 ca = *(const float4*)(g_CA + idx * 4);
            float4 cb = *(const float4*)(g_CB + idx * 4);
            float sx = fmaxf(fmaf(a4.x, ca.x, cb.x), 0.f);
            float sy = fmaxf(fmaf(a4.y, ca.y, cb.y), 0.f);
            float sz = fmaxf(fmaf(a4.z, ca.z, cb.z), 0.f);
            float sw = fmaxf(fmaf(a4.w, ca.w, cb.w), 0.f);
            float tx = fmaxf(fmaf(b4.x, ca.x, cb.x), 0.f);
            float ty = fmaxf(fmaf(b4.y, ca.y, cb.y), 0.f);
            float tz = fmaxf(fmaf(b4.z, ca.z, cb.z), 0.f);
            float tw = fmaxf(fmaf(b4.w, ca.w, cb.w), 0.f);
            acc += sx * tx + sy * ty + sz * tz + sw * tw;
        }
        accv[q] = acc;
    }
#pragma unroll
    for (int q = 0; q < 2; q++) {
#pragma unroll
        for (int o = 16; o; o >>= 1)
            accv[q] += __shfl_xor_sync(0xffffffffu, accv[q], o);
    }
    if (lane == 0) {
        out[e0] = accv[0];
        if (ne == 2) out[e0 + 1] = accv[1];
    }
}

// ---------------------------------------------------------------------------
// Launch
// ---------------------------------------------------------------------------
extern "C" void kernel_launch(void* const* d_in, const int* in_sizes, int n_in,
                              void* d_out, int out_size)
{
    const float* x     = (const float*)d_in[0];
    const int*   ei    = (const int*)d_in[1];
    const int*   eli   = (const int*)d_in[2];
    const float* Wl    = (const float*)d_in[3];
    const float* Wr    = (const float*)d_in[4];
    const float* att   = (const float*)d_in[5];
    // d_in[6] = bias: cancels under BatchNorm (mean-subtracted), unused
    const float* gamma = (const float*)d_in[7];
    const float* beta  = (const float*)d_in[8];
    float* out = (float*)d_out;

    const int N  = in_sizes[0] / INCH;
    const int E  = in_sizes[1] / 2;
    const int EL = in_sizes[2] / 2;
    const int* src = ei;
    const int* dst = ei + E;
    const int nb = (N + 255) / 256;

    k_zero<<<(N + 255) / 256, 256>>>(N);

    {
        dim3 grid(8, (N + 127) / 128);
        k_gemm<<<grid, 256>>>(x, Wl, Wr, N);
    }

    k_hist<<<(E + 255) / 256, 256>>>(dst, E);
    k_scan_part<<<nb, 256>>>(N);
    k_scan_final<<<nb, 256>>>(N, nb);
    k_scatter<<<(E + 255) / 256, 256>>>(src, dst, E);

    k_edge<<<(N * 32 + 255) / 256, 256>>>(att, N);

    {
        int rows_per = 40;
        int blocks = (N + rows_per - 1) / rows_per;
        k_bn_stats<<<blocks, 512>>>(N, rows_per);
        k_bn_coef<<<1, HC>>>(gamma, beta, 1.0f / (float)N);
    }

    {
        int warps = (EL + 1) / 2;
        k_score<<<(warps * 32 + 255) / 256, 256>>>(eli, EL, out);
    }
}